// round 6
// baseline (speedup 1.0000x reference)
#include <cuda_runtime.h>
#include <cstdint>

#define TOK   8192
#define DIMN  512
#define SEQ   512
#define NBAT  16
#define FFD   2048
#define CBSZ  8192
#define CBD   64
#define NSPLIT 4

__device__ float g_h  [TOK * DIMN];
__device__ float g_lnb[TOK * DIMN];
__device__ float g_qb [TOK * DIMN];
__device__ float g_kb [TOK * DIMN];
__device__ float g_vb [TOK * DIMN];
__device__ float g_att[TOK * DIMN];
__device__ float g_ffb[TOK * FFD];
__device__ float g_z  [TOK * CBD];
__device__ float g_cn [CBSZ];
__device__ float g_bv [NSPLIT][TOK];
__device__ int   g_bc [NSPLIT][TOK];
__device__ int   g_idx[TOK];
__device__ float g_part[NBAT];

enum { EPI_NONE = 0, EPI_BIAS = 1, EPI_BIAS_POS = 2, EPI_RES = 3,
       EPI_RES_BIAS = 4, EPI_GELU_BIAS = 5 };

__device__ __forceinline__ float gelu_f(float x) {
    float x3 = x * x * x;
    float t  = tanhf(0.7978845608028654f * (x + 0.044715f * x3));
    return 0.5f * x * (1.0f + t);
}

__device__ __forceinline__ float to_tf32(float x) {
    float r;
    asm("cvt.rna.tf32.f32 %0, %1;" : "=f"(r) : "f"(x));
    return r;
}

// m16n8k8 tf32 MMA, D += A*B
__device__ __forceinline__ void mma168(float* d, const uint32_t* a,
                                       uint32_t b0, uint32_t b1) {
    asm volatile(
        "mma.sync.aligned.m16n8k8.row.col.f32.tf32.tf32.f32 "
        "{%0,%1,%2,%3}, {%4,%5,%6,%7}, {%8,%9}, {%0,%1,%2,%3};"
        : "+f"(d[0]), "+f"(d[1]), "+f"(d[2]), "+f"(d[3])
        : "r"(a[0]), "r"(a[1]), "r"(a[2]), "r"(a[3]), "r"(b0), "r"(b1));
}

// ---------------------------------------------------------------------------
// tf32x3 GEMM, double-buffered smem: C[M,N] = A[M,K] @ B[K,N] (+epilogue).
// 128x128 CTA tile, BK=16, 8 warps each 32(m)x64(n), 2 smem buffers.
// Per buffer (floats): Ab[128][20], As[128][20], Bb[16][136], Bs[16][136]
//   = 9472 floats; x2 buffers = 75776 bytes dynamic smem.
// ---------------------------------------------------------------------------
#define BUF_F 9472
#define TG_SMEM (2 * BUF_F * 4)

__global__ __launch_bounds__(256, 2)
void tgemm_k(const float* __restrict__ A, const float* __restrict__ B,
             float* __restrict__ C, const float* __restrict__ bias,
             const float* __restrict__ extra, int Nn, int K, int epi)
{
    extern __shared__ float smf[];

    const int tid  = threadIdx.x;
    const int lane = tid & 31;
    const int w    = tid >> 5;
    const int wm   = w & 3;
    const int wn   = w >> 2;
    const int row0 = blockIdx.y * 128;
    const int col0 = blockIdx.x * 128;
    const int m0w  = wm * 32;
    const int n0w  = wn * 64;
    const int g    = lane >> 2;
    const int tg   = lane & 3;

    // loader indices (fixed per thread)
    const int lar = tid >> 2;               // A row for v=0 (v=1 adds 64)
    const int lakq = (tid & 3) << 2;        // A k quad
    const int lbk = tid >> 5;               // B k row for v=0 (v=1 adds 8)
    const int lbn = (tid & 31) << 2;        // B col quad
    const bool inb = (col0 + lbn) < Nn;

    float acc[2][8][4];
#pragma unroll
    for (int i = 0; i < 2; i++)
#pragma unroll
        for (int j = 0; j < 8; j++)
#pragma unroll
            for (int q = 0; q < 4; q++) acc[i][j][q] = 0.f;

    float4 pa[2], pb[2];

    // ---- prologue: load + store chunk 0 into buffer 0 ----
#pragma unroll
    for (int v = 0; v < 2; v++) {
        pa[v] = *(const float4*)(A + (long long)(row0 + lar + v * 64) * K + lakq);
        pb[v] = make_float4(0.f, 0.f, 0.f, 0.f);
        if (inb)
            pb[v] = *(const float4*)(B + (long long)(lbk + v * 8) * Nn + col0 + lbn);
    }
    {
        float* Ab = smf;
        float* As = smf + 2560;
        float* Bb = smf + 5120;
        float* Bs = smf + 7296;
#pragma unroll
        for (int v = 0; v < 2; v++) {
            float4 bg, smv;
            bg.x = to_tf32(pa[v].x); smv.x = to_tf32(pa[v].x - bg.x);
            bg.y = to_tf32(pa[v].y); smv.y = to_tf32(pa[v].y - bg.y);
            bg.z = to_tf32(pa[v].z); smv.z = to_tf32(pa[v].z - bg.z);
            bg.w = to_tf32(pa[v].w); smv.w = to_tf32(pa[v].w - bg.w);
            int ro = (lar + v * 64) * 20 + lakq;
            *(float4*)(Ab + ro) = bg;
            *(float4*)(As + ro) = smv;
            float4 bgb, smb;
            bgb.x = to_tf32(pb[v].x); smb.x = to_tf32(pb[v].x - bgb.x);
            bgb.y = to_tf32(pb[v].y); smb.y = to_tf32(pb[v].y - bgb.y);
            bgb.z = to_tf32(pb[v].z); smb.z = to_tf32(pb[v].z - bgb.z);
            bgb.w = to_tf32(pb[v].w); smb.w = to_tf32(pb[v].w - bgb.w);
            int bo = (lbk + v * 8) * 136 + lbn;
            *(float4*)(Bb + bo) = bgb;
            *(float4*)(Bs + bo) = smb;
        }
    }
    __syncthreads();

    const int nc = K >> 4;
    for (int c = 0; c < nc; c++) {
        const int p = c & 1;
        float* Ab = smf + p * BUF_F;
        float* As = Ab + 2560;
        float* Bb = Ab + 5120;
        float* Bs = Ab + 7296;

        // prefetch chunk c+1 from gmem
        if (c + 1 < nc) {
            const int k0 = (c + 1) << 4;
#pragma unroll
            for (int v = 0; v < 2; v++) {
                pa[v] = *(const float4*)(A + (long long)(row0 + lar + v * 64) * K + k0 + lakq);
                pb[v] = make_float4(0.f, 0.f, 0.f, 0.f);
                if (inb)
                    pb[v] = *(const float4*)(B + (long long)(k0 + lbk + v * 8) * Nn + col0 + lbn);
            }
        }

        // MMA on buffer p (2 k8 groups)
#pragma unroll
        for (int ks = 0; ks < 2; ks++) {
            const int kl = ks << 3;
            uint32_t fab[2][4], fas[2][4];
#pragma unroll
            for (int i = 0; i < 2; i++) {
                int rb = m0w + i * 16 + g;
                fab[i][0] = __float_as_uint(Ab[rb * 20 + kl + tg]);
                fab[i][1] = __float_as_uint(Ab[(rb + 8) * 20 + kl + tg]);
                fab[i][2] = __float_as_uint(Ab[rb * 20 + kl + tg + 4]);
                fab[i][3] = __float_as_uint(Ab[(rb + 8) * 20 + kl + tg + 4]);
                fas[i][0] = __float_as_uint(As[rb * 20 + kl + tg]);
                fas[i][1] = __float_as_uint(As[(rb + 8) * 20 + kl + tg]);
                fas[i][2] = __float_as_uint(As[rb * 20 + kl + tg + 4]);
                fas[i][3] = __float_as_uint(As[(rb + 8) * 20 + kl + tg + 4]);
            }
#pragma unroll
            for (int j = 0; j < 8; j++) {
                int nb = n0w + j * 8 + g;
                uint32_t bb0 = __float_as_uint(Bb[(kl + tg) * 136 + nb]);
                uint32_t bb1 = __float_as_uint(Bb[(kl + 4 + tg) * 136 + nb]);
                uint32_t bs0 = __float_as_uint(Bs[(kl + tg) * 136 + nb]);
                uint32_t bs1 = __float_as_uint(Bs[(kl + 4 + tg) * 136 + nb]);
#pragma unroll
                for (int i = 0; i < 2; i++) {
                    mma168(acc[i][j], fab[i], bb0, bb1);
                    mma168(acc[i][j], fab[i], bs0, bs1);
                    mma168(acc[i][j], fas[i], bb0, bb1);
                }
            }
        }

        // store chunk c+1 into the other buffer (overlaps other warps' MMAs)
        if (c + 1 < nc) {
            float* Ab2 = smf + (p ^ 1) * BUF_F;
            float* As2 = Ab2 + 2560;
            float* Bb2 = Ab2 + 5120;
            float* Bs2 = Ab2 + 7296;
#pragma unroll
            for (int v = 0; v < 2; v++) {
                float4 bg, smv;
                bg.x = to_tf32(pa[v].x); smv.x = to_tf32(pa[v].x - bg.x);
                bg.y = to_tf32(pa[v].y); smv.y = to_tf32(pa[v].y - bg.y);
                bg.z = to_tf32(pa[v].z); smv.z = to_tf32(pa[v].z - bg.z);
                bg.w = to_tf32(pa[v].w); smv.w = to_tf32(pa[v].w - bg.w);
                int ro = (lar + v * 64) * 20 + lakq;
                *(float4*)(Ab2 + ro) = bg;
                *(float4*)(As2 + ro) = smv;
                float4 bgb, smb;
                bgb.x = to_tf32(pb[v].x); smb.x = to_tf32(pb[v].x - bgb.x);
                bgb.y = to_tf32(pb[v].y); smb.y = to_tf32(pb[v].y - bgb.y);
                bgb.z = to_tf32(pb[v].z); smb.z = to_tf32(pb[v].z - bgb.z);
                bgb.w = to_tf32(pb[v].w); smb.w = to_tf32(pb[v].w - bgb.w);
                int bo = (lbk + v * 8) * 136 + lbn;
                *(float4*)(Bb2 + bo) = bgb;
                *(float4*)(Bs2 + bo) = smb;
            }
            __syncthreads();
        }
    }

    // ---- epilogue ----
#pragma unroll
    for (int i = 0; i < 2; i++) {
        int r = row0 + m0w + i * 16 + g;
#pragma unroll
        for (int j = 0; j < 8; j++) {
            int cc = col0 + n0w + j * 8 + 2 * tg;
            if (cc >= Nn) continue;
            float2 v0 = make_float2(acc[i][j][0], acc[i][j][1]);
            float2 v1 = make_float2(acc[i][j][2], acc[i][j][3]);
            if (epi == EPI_BIAS || epi == EPI_RES_BIAS ||
                epi == EPI_GELU_BIAS || epi == EPI_BIAS_POS) {
                float2 b2 = *(const float2*)(bias + cc);
                v0.x += b2.x; v0.y += b2.y;
                v1.x += b2.x; v1.y += b2.y;
            }
            if (epi == EPI_BIAS_POS) {
                float2 p0 = *(const float2*)(extra + (long long)(r & (SEQ - 1)) * Nn + cc);
                float2 p1 = *(const float2*)(extra + (long long)((r + 8) & (SEQ - 1)) * Nn + cc);
                v0.x += p0.x; v0.y += p0.y;
                v1.x += p1.x; v1.y += p1.y;
            }
            if (epi == EPI_RES || epi == EPI_RES_BIAS) {
                float2 e0 = *(const float2*)(extra + (long long)r * Nn + cc);
                float2 e1 = *(const float2*)(extra + (long long)(r + 8) * Nn + cc);
                v0.x += e0.x; v0.y += e0.y;
                v1.x += e1.x; v1.y += e1.y;
            }
            if (epi == EPI_GELU_BIAS) {
                v0.x = gelu_f(v0.x); v0.y = gelu_f(v0.y);
                v1.x = gelu_f(v1.x); v1.y = gelu_f(v1.y);
            }
            *(float2*)(C + (long long)r * Nn + cc) = v0;
            *(float2*)(C + (long long)(r + 8) * Nn + cc) = v1;
        }
    }
}

// ---------------------------------------------------------------------------
// LayerNorm (row = 512)
// ---------------------------------------------------------------------------
__global__ void layernorm_k(const float* __restrict__ X, float* __restrict__ Y,
                            const float* __restrict__ gg, const float* __restrict__ bb)
{
    __shared__ float sm[16];
    const int row = blockIdx.x;
    const int t   = threadIdx.x;
    const float* x = X + (long long)row * DIMN;
    float v0 = x[t], v1 = x[t + 256];
    float s = v0 + v1;
    float q = v0 * v0 + v1 * v1;
#pragma unroll
    for (int off = 16; off; off >>= 1) {
        s += __shfl_xor_sync(0xffffffffu, s, off);
        q += __shfl_xor_sync(0xffffffffu, q, off);
    }
    if ((t & 31) == 0) { sm[t >> 5] = s; sm[8 + (t >> 5)] = q; }
    __syncthreads();
    float S = 0.f, Q = 0.f;
#pragma unroll
    for (int i = 0; i < 8; i++) { S += sm[i]; Q += sm[8 + i]; }
    float mu  = S * (1.0f / DIMN);
    float var = Q * (1.0f / DIMN) - mu * mu;
    float inv = 1.0f / sqrtf(var + 1e-5f);
    Y[(long long)row * DIMN + t]       = (v0 - mu) * inv * gg[t]       + bb[t];
    Y[(long long)row * DIMN + t + 256] = (v1 - mu) * inv * gg[t + 256] + bb[t + 256];
}

// ---------------------------------------------------------------------------
// Fused flash attention (SIMT fp32)
// ---------------------------------------------------------------------------
__global__ __launch_bounds__(256)
void fattn_k(const float* __restrict__ Q, const float* __restrict__ K,
             const float* __restrict__ V, float* __restrict__ O)
{
    extern __shared__ float smbuf[];
    float (*Qs)[65] = (float (*)[65])(smbuf);
    float (*Ks)[65] = (float (*)[65])(smbuf + 4160);
    float (*Vs)[65] = (float (*)[65])(smbuf + 8320);
    float (*Ps)[65] = (float (*)[65])(smbuf + 12480);

    const int qt = blockIdx.x, bh = blockIdx.y;
    const int b = bh >> 3, h = bh & 7;
    const int tid = threadIdx.x;
    const int ty = tid >> 4, tx = tid & 15;

#pragma unroll
    for (int v = 0; v < 4; v++) {
        int idx = tid + v * 256;
        int r = idx >> 4, c = (idx & 15) << 2;
        float4 t = *(const float4*)(Q + (long long)(b * SEQ + qt * 64 + r) * DIMN + h * 64 + c);
        Qs[r][c] = t.x; Qs[r][c + 1] = t.y; Qs[r][c + 2] = t.z; Qs[r][c + 3] = t.w;
    }

    float m[4], l[4], o[4][4];
#pragma unroll
    for (int i = 0; i < 4; i++) {
        m[i] = -1e30f; l[i] = 0.f;
#pragma unroll
        for (int j = 0; j < 4; j++) o[i][j] = 0.f;
    }

    for (int kt = 0; kt < 8; kt++) {
#pragma unroll
        for (int v = 0; v < 4; v++) {
            int idx = tid + v * 256;
            int r = idx >> 4, c = (idx & 15) << 2;
            float4 tk = *(const float4*)(K + (long long)(b * SEQ + kt * 64 + r) * DIMN + h * 64 + c);
            Ks[r][c] = tk.x; Ks[r][c + 1] = tk.y; Ks[r][c + 2] = tk.z; Ks[r][c + 3] = tk.w;
            float4 tv = *(const float4*)(V + (long long)(b * SEQ + kt * 64 + r) * DIMN + h * 64 + c);
            Vs[r][c] = tv.x; Vs[r][c + 1] = tv.y; Vs[r][c + 2] = tv.z; Vs[r][c + 3] = tv.w;
        }
        __syncthreads();

        float s[4][4] = {};
#pragma unroll 8
        for (int d = 0; d < 64; d++) {
            float qv[4], kv[4];
#pragma unroll
            for (int i = 0; i < 4; i++) qv[i] = Qs[ty * 4 + i][d];
#pragma unroll
            for (int j = 0; j < 4; j++) kv[j] = Ks[tx * 4 + j][d];
#pragma unroll
            for (int i = 0; i < 4; i++)
#pragma unroll
                for (int j = 0; j < 4; j++) s[i][j] += qv[i] * kv[j];
        }

        float p[4][4];
#pragma unroll
        for (int i = 0; i < 4; i++) {
            float rm = -1e30f;
#pragma unroll
            for (int j = 0; j < 4; j++) { s[i][j] *= 0.125f; rm = fmaxf(rm, s[i][j]); }
#pragma unroll
            for (int off = 8; off; off >>= 1)
                rm = fmaxf(rm, __shfl_xor_sync(0xffffffffu, rm, off));
            float mn = fmaxf(m[i], rm);
            float sc = __expf(m[i] - mn);
            float rs = 0.f;
#pragma unroll
            for (int j = 0; j < 4; j++) { p[i][j] = __expf(s[i][j] - mn); rs += p[i][j]; }
#pragma unroll
            for (int off = 8; off; off >>= 1)
                rs += __shfl_xor_sync(0xffffffffu, rs, off);
            l[i] = l[i] * sc + rs;
#pragma unroll
            for (int j = 0; j < 4; j++) o[i][j] *= sc;
            m[i] = mn;
        }

#pragma unroll
        for (int i = 0; i < 4; i++)
#pragma unroll
            for (int j = 0; j < 4; j++) Ps[ty * 4 + i][tx * 4 + j] = p[i][j];
        __syncthreads();

#pragma unroll 8
        for (int kk = 0; kk < 64; kk++) {
            float a[4], vv[4];
#pragma unroll
            for (int i = 0; i < 4; i++) a[i] = Ps[ty * 4 + i][kk];
#pragma unroll
            for (int j = 0; j < 4; j++) vv[j] = Vs[kk][tx * 4 + j];
#pragma unroll
            for (int i = 0; i < 4; i++)
#pragma unroll
                for (int j = 0; j < 4; j++) o[i][j] += a[i] * vv[j];
        }
        __syncthreads();
    }

#pragma unroll
    for (int i = 0; i < 4; i++) {
        int row = b * SEQ + qt * 64 + ty * 4 + i;
        float inv = 1.0f / l[i];
        float4 t = make_float4(o[i][0] * inv, o[i][1] * inv,
                               o[i][2] * inv, o[i][3] * inv);
        *(float4*)(O + (long long)row * DIMN + h * 64 + tx * 4) = t;
    }
}

// ---------------------------------------------------------------------------
// VQ
// ---------------------------------------------------------------------------
__global__ void cb_norm_k(const float* __restrict__ cb)
{
    int c = blockIdx.x * 256 + threadIdx.x;
    float s = 0.f;
    const float* p = cb + (long long)c * CBD;
#pragma unroll 8
    for (int d = 0; d < CBD; d++) { float v = p[d]; s += v * v; }
    g_cn[c] = 0.5f * s;
}

__global__ __launch_bounds__(256)
void vq_argmin_k(const float* __restrict__ Z, const float* __restrict__ cb)
{
    const int zb = blockIdx.x;
    const int sp = blockIdx.y;
    __shared__ float Zs[64][65];
    __shared__ float Cs[64][65];
    const int tid = threadIdx.x;
    const int ty = tid >> 4, tx = tid & 15;
#pragma unroll
    for (int v = 0; v < 4; v++) {
        int idx = tid + v * 256;
        int r = idx >> 4, c = (idx & 15) << 2;
        float4 t = *(const float4*)(Z + (long long)(zb * 64 + r) * CBD + c);
        Zs[r][c] = t.x; Zs[r][c + 1] = t.y; Zs[r][c + 2] = t.z; Zs[r][c + 3] = t.w;
    }
    __syncthreads();

    float bestv[4]; int bestc[4];
#pragma unroll
    for (int i = 0; i < 4; i++) { bestv[i] = -1e30f; bestc[i] = sp * (CBSZ / NSPLIT); }

    const int cbeg = sp * (CBSZ / NSPLIT);
    const int cend = cbeg + (CBSZ / NSPLIT);
    for (int c0 = cbeg; c0 < cend; c0 += 64) {
#pragma unroll
        for (int v = 0; v < 4; v++) {
            int idx = tid + v * 256;
            int r = idx >> 4, c = (idx & 15) << 2;
            float4 t = *(const float4*)(cb + (long long)(c0 + r) * CBD + c);
            Cs[r][c] = t.x; Cs[r][c + 1] = t.y; Cs[r][c + 2] = t.z; Cs[r][c + 3] = t.w;
        }
        __syncthreads();
        float acc[4][4] = {};
#pragma unroll 8
        for (int d = 0; d < 64; d++) {
            float zv[4], cv[4];
#pragma unroll
            for (int i = 0; i < 4; i++) zv[i] = Zs[ty * 4 + i][d];
#pragma unroll
            for (int j = 0; j < 4; j++) cv[j] = Cs[tx * 4 + j][d];
#pragma unroll
            for (int i = 0; i < 4; i++)
#pragma unroll
                for (int j = 0; j < 4; j++) acc[i][j] += zv[i] * cv[j];
        }
#pragma unroll
        for (int i = 0; i < 4; i++)
#pragma unroll
            for (int j = 0; j < 4; j++) {
                int c = c0 + tx * 4 + j;
                float scv = acc[i][j] - g_cn[c];
                if (scv > bestv[i] || (scv == bestv[i] && c < bestc[i])) {
                    bestv[i] = scv; bestc[i] = c;
                }
            }
        __syncthreads();
    }
#pragma unroll
    for (int i = 0; i < 4; i++) {
        float v = bestv[i]; int c = bestc[i];
#pragma unroll
        for (int off = 8; off; off >>= 1) {
            float ov = __shfl_xor_sync(0xffffffffu, v, off);
            int   oc = __shfl_xor_sync(0xffffffffu, c, off);
            if (ov > v || (ov == v && oc < c)) { v = ov; c = oc; }
        }
        if (tx == 0) {
            g_bv[sp][zb * 64 + ty * 4 + i] = v;
            g_bc[sp][zb * 64 + ty * 4 + i] = c;
        }
    }
}

__global__ void vq_combine_k()
{
    int t = blockIdx.x * 256 + threadIdx.x;
    float bv = g_bv[0][t]; int bc = g_bc[0][t];
#pragma unroll
    for (int s = 1; s < NSPLIT; s++) {
        float v = g_bv[s][t]; int c = g_bc[s][t];
        if (v > bv) { bv = v; bc = c; }
    }
    g_idx[t] = bc;
}

__global__ void vq_reduce_k(const float* __restrict__ cb,
                            const float* __restrict__ Z,
                            float* __restrict__ out)
{
    __shared__ float ssum[256];
    __shared__ float sloss[256];
    const int b = blockIdx.x;
    const int tid = threadIdx.x;
    const int d = tid & 63;
    const int sg = tid >> 6;
    float sum = 0.f, loss = 0.f;
    for (int s = sg; s < SEQ; s += 4) {
        int c = g_idx[b * SEQ + s];
        float qv = cb[(long long)c * CBD + d];
        float zv = Z[((long long)b * SEQ + s) * CBD + d];
        sum += qv;
        float dd = qv - zv;
        loss += dd * dd;
    }
    ssum[tid] = sum; sloss[tid] = loss;
    __syncthreads();
    if (tid < 64)
        out[b * CBD + tid] = ssum[tid] + ssum[tid + 64] + ssum[tid + 128] + ssum[tid + 192];
    for (int st = 128; st > 0; st >>= 1) {
        if (tid < st) sloss[tid] += sloss[tid + st];
        __syncthreads();
    }
    if (tid == 0) g_part[b] = sloss[0];
}

__global__ void vq_finish_k(float* __restrict__ out, int out_size)
{
    if (threadIdx.x == 0 && out_size > NBAT * CBD) {
        float s = 0.f;
        for (int i = 0; i < NBAT; i++) s += g_part[i];
        out[NBAT * CBD] = s / (float)(TOK * CBD);
    }
}

// ---------------------------------------------------------------------------
// Launch
// ---------------------------------------------------------------------------
extern "C" void kernel_launch(void* const* d_in, const int* in_sizes, int n_in,
                              void* d_out, int out_size)
{
    (void)in_sizes; (void)n_in;
    const float* x    = (const float*)d_in[0];
    const float* w_in = (const float*)d_in[1];
    const float* b_in = (const float*)d_in[2];
    const float* pos  = (const float*)d_in[3];
    const float* ln1g = (const float*)d_in[4];
    const float* ln1b = (const float*)d_in[5];
    const float* wq   = (const float*)d_in[6];
    const float* wk   = (const float*)d_in[7];
    const float* wv   = (const float*)d_in[8];
    const float* wo   = (const float*)d_in[9];
    const float* ln2g = (const float*)d_in[10];
    const float* ln2b = (const float*)d_in[11];
    const float* fw1  = (const float*)d_in[12];
    const float* fb1  = (const float*)d_in[13];
    const float* fw2  = (const float*)d_in[14];
    const float* fb2  = (const float*)d_in[15];
    const float* lnfg = (const float*)d_in[16];
    const float* lnfb = (const float*)d_in[17];
    const float* wout = (const float*)d_in[18];
    const float* bout = (const float*)d_in[19];
    const float* cbk  = (const float*)d_in[20];
    float* out = (float*)d_out;

    float *h, *ln, *qb, *kb, *vb, *att, *ff, *z;
    cudaGetSymbolAddress((void**)&h,   g_h);
    cudaGetSymbolAddress((void**)&ln,  g_lnb);
    cudaGetSymbolAddress((void**)&qb,  g_qb);
    cudaGetSymbolAddress((void**)&kb,  g_kb);
    cudaGetSymbolAddress((void**)&vb,  g_vb);
    cudaGetSymbolAddress((void**)&att, g_att);
    cudaGetSymbolAddress((void**)&ff,  g_ffb);
    cudaGetSymbolAddress((void**)&z,   g_z);

    cudaFuncSetAttribute(tgemm_k, cudaFuncAttributeMaxDynamicSharedMemorySize, TG_SMEM);
    cudaFuncSetAttribute(fattn_k, cudaFuncAttributeMaxDynamicSharedMemorySize,
                         16640 * (int)sizeof(float));

    const dim3 g512(4, 64), g2048(16, 64), g64(1, 64);

    tgemm_k<<<g512, 256, TG_SMEM>>>(x, w_in, h, b_in, pos, DIMN, DIMN, EPI_BIAS_POS);

    for (int l = 0; l < 4; l++) {
        layernorm_k<<<TOK, 256>>>(h, ln, ln1g + l * DIMN, ln1b + l * DIMN);
        tgemm_k<<<g512, 256, TG_SMEM>>>(ln, wq + (long long)l * DIMN * DIMN, qb, nullptr, nullptr, DIMN, DIMN, EPI_NONE);
        tgemm_k<<<g512, 256, TG_SMEM>>>(ln, wk + (long long)l * DIMN * DIMN, kb, nullptr, nullptr, DIMN, DIMN, EPI_NONE);
        tgemm_k<<<g512, 256, TG_SMEM>>>(ln, wv + (long long)l * DIMN * DIMN, vb, nullptr, nullptr, DIMN, DIMN, EPI_NONE);
        fattn_k<<<dim3(8, 128), 256, 16640 * sizeof(float)>>>(qb, kb, vb, att);
        tgemm_k<<<g512, 256, TG_SMEM>>>(att, wo + (long long)l * DIMN * DIMN, h, nullptr, h, DIMN, DIMN, EPI_RES);
        layernorm_k<<<TOK, 256>>>(h, ln, ln2g + l * DIMN, ln2b + l * DIMN);
        tgemm_k<<<g2048, 256, TG_SMEM>>>(ln, fw1 + (long long)l * DIMN * FFD, ff, fb1 + l * FFD, nullptr, FFD, DIMN, EPI_GELU_BIAS);
        tgemm_k<<<g512, 256, TG_SMEM>>>(ff, fw2 + (long long)l * FFD * DIMN, h, fb2 + l * DIMN, h, DIMN, FFD, EPI_RES_BIAS);
    }

    layernorm_k<<<TOK, 256>>>(h, ln, lnfg, lnfb);
    tgemm_k<<<g64, 256, TG_SMEM>>>(ln, wout, z, bout, nullptr, CBD, DIMN, EPI_BIAS);

    cb_norm_k<<<CBSZ / 256, 256>>>(cbk);
    vq_argmin_k<<<dim3(TOK / 64, NSPLIT), 256>>>(z, cbk);
    vq_combine_k<<<TOK / 256, 256>>>();
    vq_reduce_k<<<NBAT, 256>>>(cbk, z, out);
    vq_finish_k<<<1, 32>>>(out, out_size);
}

// round 7
// speedup vs baseline: 1.3439x; 1.3439x over previous
#include <cuda_runtime.h>
#include <cuda_fp16.h>
#include <cstdint>

#define TOK   8192
#define DIMN  512
#define SEQ   512
#define NBAT  16
#define FFD   2048
#define CBSZ  8192
#define CBD   64
#define NSPLIT 4

__device__ float g_h  [TOK * DIMN];
__device__ float g_lnb[TOK * DIMN];
__device__ float g_qb [TOK * DIMN];
__device__ float g_kb [TOK * DIMN];
__device__ float g_vb [TOK * DIMN];
__device__ float g_att[TOK * DIMN];
__device__ float g_ffb[TOK * FFD];
__device__ float g_z  [TOK * CBD];
__device__ float g_cn [CBSZ];
__device__ float g_bv [NSPLIT][TOK];
__device__ int   g_bc [NSPLIT][TOK];
__device__ int   g_idx[TOK];
__device__ float g_part[NBAT];

enum { EPI_NONE = 0, EPI_BIAS = 1, EPI_BIAS_POS = 2, EPI_RES = 3,
       EPI_RES_BIAS = 4, EPI_GELU_BIAS = 5 };

__device__ __forceinline__ float gelu_f(float x) {
    float x3 = x * x * x;
    float t  = tanhf(0.7978845608028654f * (x + 0.044715f * x3));
    return 0.5f * x * (1.0f + t);
}

// pack two fp32 into (big half2) and (small half2)
__device__ __forceinline__ void split2(float x, float y,
                                       uint32_t& big, uint32_t& sml) {
    half bx = __float2half_rn(x);
    half by = __float2half_rn(y);
    half sx = __float2half_rn(x - __half2float(bx));
    half sy = __float2half_rn(y - __half2float(by));
    half2 b = __halves2half2(bx, by);
    half2 s = __halves2half2(sx, sy);
    big = *(uint32_t*)&b;
    sml = *(uint32_t*)&s;
}

// m16n8k16 fp16 MMA, f32 accum: D += A*B
__device__ __forceinline__ void mma16816(float* d, const uint32_t* a,
                                         uint32_t b0, uint32_t b1) {
    asm volatile(
        "mma.sync.aligned.m16n8k16.row.col.f32.f16.f16.f32 "
        "{%0,%1,%2,%3}, {%4,%5,%6,%7}, {%8,%9}, {%0,%1,%2,%3};"
        : "+f"(d[0]), "+f"(d[1]), "+f"(d[2]), "+f"(d[3])
        : "r"(a[0]), "r"(a[1]), "r"(a[2]), "r"(a[3]), "r"(b0), "r"(b1));
}

// ---------------------------------------------------------------------------
// fp16x3 GEMM, double-buffered: C[M,N] = A[M,K] @ B[K,N] (+epilogue).
// 128x128 CTA tile, BK=32, 8 warps each 32(m)x64(n).
// smem per buffer (uint32 words): Ab[128][20], As[128][20],
//                                 Bb[128][20], Bs[128][20]  (n-major, k half2)
//   = 10240 words = 40KB; x2 buffers = 80KB dynamic smem.
// ---------------------------------------------------------------------------
#define BUF_W 10240
#define TG_SMEM (2 * BUF_W * 4)

__global__ __launch_bounds__(256, 2)
void tgemm_k(const float* __restrict__ A, const float* __restrict__ B,
             float* __restrict__ C, const float* __restrict__ bias,
             const float* __restrict__ extra, int Nn, int K, int epi)
{
    extern __shared__ uint32_t smw[];

    const int tid  = threadIdx.x;
    const int lane = tid & 31;
    const int w    = tid >> 5;
    const int wm   = w & 3;
    const int wn   = w >> 2;
    const int row0 = blockIdx.y * 128;
    const int col0 = blockIdx.x * 128;
    const int m0w  = wm * 32;
    const int n0w  = wn * 64;
    const int g    = lane >> 2;
    const int tg   = lane & 3;

    // A loader indices: thread covers rows (tid>>2, +64), k quads (tid&3)*4 +{0,16}
    const int lar  = tid >> 2;
    const int lakq = (tid & 3) << 2;
    // B loader: thread covers n = tid&127, k half (tid>>7)*16
    const int lbn  = tid & 127;
    const int lbkh = tid >> 7;
    const bool inb = (col0 + lbn) < Nn;

    float acc[2][8][4];
#pragma unroll
    for (int i = 0; i < 2; i++)
#pragma unroll
        for (int j = 0; j < 8; j++)
#pragma unroll
            for (int q = 0; q < 4; q++) acc[i][j][q] = 0.f;

    float4 pa[4];          // A: 2 rows x 2 kb
    float  pbv[16];        // B: 16 k values at column lbn

    // ---------------- stage helpers (macros keep regs tight) ---------------
#define LOAD_CHUNK(k0)                                                        \
    {                                                                         \
        _Pragma("unroll")                                                     \
        for (int v = 0; v < 2; v++)                                           \
            _Pragma("unroll")                                                 \
            for (int kb = 0; kb < 2; kb++)                                    \
                pa[v * 2 + kb] = *(const float4*)(A +                         \
                    (long long)(row0 + lar + v * 64) * K + (k0) + kb * 16 + lakq); \
        _Pragma("unroll")                                                     \
        for (int kk = 0; kk < 16; kk++) {                                     \
            pbv[kk] = 0.f;                                                    \
            if (inb)                                                          \
                pbv[kk] = B[(long long)((k0) + lbkh * 16 + kk) * Nn + col0 + lbn]; \
        }                                                                     \
    }

#define STORE_CHUNK(base)                                                     \
    {                                                                         \
        uint32_t* Abw = (base);                                               \
        uint32_t* Asw = (base) + 2560;                                        \
        uint32_t* Bbw = (base) + 5120;                                        \
        uint32_t* Bsw = (base) + 7680;                                        \
        _Pragma("unroll")                                                     \
        for (int v = 0; v < 2; v++)                                           \
            _Pragma("unroll")                                                 \
            for (int kb = 0; kb < 2; kb++) {                                  \
                float4 t = pa[v * 2 + kb];                                    \
                uint32_t b0, s0, b1, s1;                                      \
                split2(t.x, t.y, b0, s0);                                     \
                split2(t.z, t.w, b1, s1);                                     \
                int wo = (lar + v * 64) * 20 + kb * 8 + (lakq >> 1);          \
                Abw[wo] = b0; Abw[wo + 1] = b1;                               \
                Asw[wo] = s0; Asw[wo + 1] = s1;                               \
            }                                                                 \
        uint32_t bw[8], sw[8];                                                \
        _Pragma("unroll")                                                     \
        for (int p = 0; p < 8; p++)                                           \
            split2(pbv[2 * p], pbv[2 * p + 1], bw[p], sw[p]);                 \
        int bo = lbn * 20 + lbkh * 8;                                         \
        *(uint4*)(Bbw + bo)     = make_uint4(bw[0], bw[1], bw[2], bw[3]);     \
        *(uint4*)(Bbw + bo + 4) = make_uint4(bw[4], bw[5], bw[6], bw[7]);     \
        *(uint4*)(Bsw + bo)     = make_uint4(sw[0], sw[1], sw[2], sw[3]);     \
        *(uint4*)(Bsw + bo + 4) = make_uint4(sw[4], sw[5], sw[6], sw[7]);     \
    }

    // ---- prologue ----
    LOAD_CHUNK(0)
    STORE_CHUNK(smw)
    __syncthreads();

    const int nc = K >> 5;
    for (int c = 0; c < nc; c++) {
        const int p = c & 1;
        uint32_t* Abw = smw + p * BUF_W;
        uint32_t* Asw = Abw + 2560;
        uint32_t* Bbw = Abw + 5120;
        uint32_t* Bsw = Abw + 7680;

        if (c + 1 < nc) LOAD_CHUNK((c + 1) << 5)

        // MMA on buffer p: 2 k16 groups
#pragma unroll
        for (int ks = 0; ks < 2; ks++) {
            const int ko = ks << 3;   // word offset of this k16 group
            uint32_t fab[2][4], fas[2][4];
#pragma unroll
            for (int i = 0; i < 2; i++) {
                int rb = m0w + i * 16 + g;
                fab[i][0] = Abw[rb * 20 + ko + tg];
                fab[i][1] = Abw[(rb + 8) * 20 + ko + tg];
                fab[i][2] = Abw[rb * 20 + ko + tg + 4];
                fab[i][3] = Abw[(rb + 8) * 20 + ko + tg + 4];
                fas[i][0] = Asw[rb * 20 + ko + tg];
                fas[i][1] = Asw[(rb + 8) * 20 + ko + tg];
                fas[i][2] = Asw[rb * 20 + ko + tg + 4];
                fas[i][3] = Asw[(rb + 8) * 20 + ko + tg + 4];
            }
#pragma unroll
            for (int j = 0; j < 8; j++) {
                int nb = n0w + j * 8 + g;
                uint32_t bb0 = Bbw[nb * 20 + ko + tg];
                uint32_t bb1 = Bbw[nb * 20 + ko + tg + 4];
                uint32_t bs0 = Bsw[nb * 20 + ko + tg];
                uint32_t bs1 = Bsw[nb * 20 + ko + tg + 4];
#pragma unroll
                for (int i = 0; i < 2; i++) {
                    mma16816(acc[i][j], fab[i], bb0, bb1);
                    mma16816(acc[i][j], fab[i], bs0, bs1);
                    mma16816(acc[i][j], fas[i], bb0, bb1);
                }
            }
        }

        if (c + 1 < nc) {
            STORE_CHUNK(smw + (p ^ 1) * BUF_W)
            __syncthreads();
        }
    }
#undef LOAD_CHUNK
#undef STORE_CHUNK

    // ---- epilogue ----
#pragma unroll
    for (int i = 0; i < 2; i++) {
        int r = row0 + m0w + i * 16 + g;
#pragma unroll
        for (int j = 0; j < 8; j++) {
            int cc = col0 + n0w + j * 8 + 2 * tg;
            if (cc >= Nn) continue;
            float2 v0 = make_float2(acc[i][j][0], acc[i][j][1]);
            float2 v1 = make_float2(acc[i][j][2], acc[i][j][3]);
            if (epi == EPI_BIAS || epi == EPI_RES_BIAS ||
                epi == EPI_GELU_BIAS || epi == EPI_BIAS_POS) {
                float2 b2 = *(const float2*)(bias + cc);
                v0.x += b2.x; v0.y += b2.y;
                v1.x += b2.x; v1.y += b2.y;
            }
            if (epi == EPI_BIAS_POS) {
                float2 p0 = *(const float2*)(extra + (long long)(r & (SEQ - 1)) * Nn + cc);
                float2 p1 = *(const float2*)(extra + (long long)((r + 8) & (SEQ - 1)) * Nn + cc);
                v0.x += p0.x; v0.y += p0.y;
                v1.x += p1.x; v1.y += p1.y;
            }
            if (epi == EPI_RES || epi == EPI_RES_BIAS) {
                float2 e0 = *(const float2*)(extra + (long long)r * Nn + cc);
                float2 e1 = *(const float2*)(extra + (long long)(r + 8) * Nn + cc);
                v0.x += e0.x; v0.y += e0.y;
                v1.x += e1.x; v1.y += e1.y;
            }
            if (epi == EPI_GELU_BIAS) {
                v0.x = gelu_f(v0.x); v0.y = gelu_f(v0.y);
                v1.x = gelu_f(v1.x); v1.y = gelu_f(v1.y);
            }
            *(float2*)(C + (long long)r * Nn + cc) = v0;
            *(float2*)(C + (long long)(r + 8) * Nn + cc) = v1;
        }
    }
}

// ---------------------------------------------------------------------------
// LayerNorm (row = 512)
// ---------------------------------------------------------------------------
__global__ void layernorm_k(const float* __restrict__ X, float* __restrict__ Y,
                            const float* __restrict__ gg, const float* __restrict__ bb)
{
    __shared__ float sm[16];
    const int row = blockIdx.x;
    const int t   = threadIdx.x;
    const float* x = X + (long long)row * DIMN;
    float v0 = x[t], v1 = x[t + 256];
    float s = v0 + v1;
    float q = v0 * v0 + v1 * v1;
#pragma unroll
    for (int off = 16; off; off >>= 1) {
        s += __shfl_xor_sync(0xffffffffu, s, off);
        q += __shfl_xor_sync(0xffffffffu, q, off);
    }
    if ((t & 31) == 0) { sm[t >> 5] = s; sm[8 + (t >> 5)] = q; }
    __syncthreads();
    float S = 0.f, Q = 0.f;
#pragma unroll
    for (int i = 0; i < 8; i++) { S += sm[i]; Q += sm[8 + i]; }
    float mu  = S * (1.0f / DIMN);
    float var = Q * (1.0f / DIMN) - mu * mu;
    float inv = 1.0f / sqrtf(var + 1e-5f);
    Y[(long long)row * DIMN + t]       = (v0 - mu) * inv * gg[t]       + bb[t];
    Y[(long long)row * DIMN + t + 256] = (v1 - mu) * inv * gg[t + 256] + bb[t + 256];
}

// ---------------------------------------------------------------------------
// Fused flash attention (SIMT fp32)
// ---------------------------------------------------------------------------
__global__ __launch_bounds__(256)
void fattn_k(const float* __restrict__ Q, const float* __restrict__ K,
             const float* __restrict__ V, float* __restrict__ O)
{
    extern __shared__ float smbuf[];
    float (*Qs)[65] = (float (*)[65])(smbuf);
    float (*Ks)[65] = (float (*)[65])(smbuf + 4160);
    float (*Vs)[65] = (float (*)[65])(smbuf + 8320);
    float (*Ps)[65] = (float (*)[65])(smbuf + 12480);

    const int qt = blockIdx.x, bh = blockIdx.y;
    const int b = bh >> 3, h = bh & 7;
    const int tid = threadIdx.x;
    const int ty = tid >> 4, tx = tid & 15;

#pragma unroll
    for (int v = 0; v < 4; v++) {
        int idx = tid + v * 256;
        int r = idx >> 4, c = (idx & 15) << 2;
        float4 t = *(const float4*)(Q + (long long)(b * SEQ + qt * 64 + r) * DIMN + h * 64 + c);
        Qs[r][c] = t.x; Qs[r][c + 1] = t.y; Qs[r][c + 2] = t.z; Qs[r][c + 3] = t.w;
    }

    float m[4], l[4], o[4][4];
#pragma unroll
    for (int i = 0; i < 4; i++) {
        m[i] = -1e30f; l[i] = 0.f;
#pragma unroll
        for (int j = 0; j < 4; j++) o[i][j] = 0.f;
    }

    for (int kt = 0; kt < 8; kt++) {
#pragma unroll
        for (int v = 0; v < 4; v++) {
            int idx = tid + v * 256;
            int r = idx >> 4, c = (idx & 15) << 2;
            float4 tk = *(const float4*)(K + (long long)(b * SEQ + kt * 64 + r) * DIMN + h * 64 + c);
            Ks[r][c] = tk.x; Ks[r][c + 1] = tk.y; Ks[r][c + 2] = tk.z; Ks[r][c + 3] = tk.w;
            float4 tv = *(const float4*)(V + (long long)(b * SEQ + kt * 64 + r) * DIMN + h * 64 + c);
            Vs[r][c] = tv.x; Vs[r][c + 1] = tv.y; Vs[r][c + 2] = tv.z; Vs[r][c + 3] = tv.w;
        }
        __syncthreads();

        float s[4][4] = {};
#pragma unroll 8
        for (int d = 0; d < 64; d++) {
            float qv[4], kv[4];
#pragma unroll
            for (int i = 0; i < 4; i++) qv[i] = Qs[ty * 4 + i][d];
#pragma unroll
            for (int j = 0; j < 4; j++) kv[j] = Ks[tx * 4 + j][d];
#pragma unroll
            for (int i = 0; i < 4; i++)
#pragma unroll
                for (int j = 0; j < 4; j++) s[i][j] += qv[i] * kv[j];
        }

        float p[4][4];
#pragma unroll
        for (int i = 0; i < 4; i++) {
            float rm = -1e30f;
#pragma unroll
            for (int j = 0; j < 4; j++) { s[i][j] *= 0.125f; rm = fmaxf(rm, s[i][j]); }
#pragma unroll
            for (int off = 8; off; off >>= 1)
                rm = fmaxf(rm, __shfl_xor_sync(0xffffffffu, rm, off));
            float mn = fmaxf(m[i], rm);
            float sc = __expf(m[i] - mn);
            float rs = 0.f;
#pragma unroll
            for (int j = 0; j < 4; j++) { p[i][j] = __expf(s[i][j] - mn); rs += p[i][j]; }
#pragma unroll
            for (int off = 8; off; off >>= 1)
                rs += __shfl_xor_sync(0xffffffffu, rs, off);
            l[i] = l[i] * sc + rs;
#pragma unroll
            for (int j = 0; j < 4; j++) o[i][j] *= sc;
            m[i] = mn;
        }

#pragma unroll
        for (int i = 0; i < 4; i++)
#pragma unroll
            for (int j = 0; j < 4; j++) Ps[ty * 4 + i][tx * 4 + j] = p[i][j];
        __syncthreads();

#pragma unroll 8
        for (int kk = 0; kk < 64; kk++) {
            float a[4], vv[4];
#pragma unroll
            for (int i = 0; i < 4; i++) a[i] = Ps[ty * 4 + i][kk];
#pragma unroll
            for (int j = 0; j < 4; j++) vv[j] = Vs[kk][tx * 4 + j];
#pragma unroll
            for (int i = 0; i < 4; i++)
#pragma unroll
                for (int j = 0; j < 4; j++) o[i][j] += a[i] * vv[j];
        }
        __syncthreads();
    }

#pragma unroll
    for (int i = 0; i < 4; i++) {
        int row = b * SEQ + qt * 64 + ty * 4 + i;
        float inv = 1.0f / l[i];
        float4 t = make_float4(o[i][0] * inv, o[i][1] * inv,
                               o[i][2] * inv, o[i][3] * inv);
        *(float4*)(O + (long long)row * DIMN + h * 64 + tx * 4) = t;
    }
}

// ---------------------------------------------------------------------------
// VQ
// ---------------------------------------------------------------------------
__global__ void cb_norm_k(const float* __restrict__ cb)
{
    int c = blockIdx.x * 256 + threadIdx.x;
    float s = 0.f;
    const float* p = cb + (long long)c * CBD;
#pragma unroll 8
    for (int d = 0; d < CBD; d++) { float v = p[d]; s += v * v; }
    g_cn[c] = 0.5f * s;
}

__global__ __launch_bounds__(256)
void vq_argmin_k(const float* __restrict__ Z, const float* __restrict__ cb)
{
    const int zb = blockIdx.x;
    const int sp = blockIdx.y;
    __shared__ float Zs[64][65];
    __shared__ float Cs[64][65];
    const int tid = threadIdx.x;
    const int ty = tid >> 4, tx = tid & 15;
#pragma unroll
    for (int v = 0; v < 4; v++) {
        int idx = tid + v * 256;
        int r = idx >> 4, c = (idx & 15) << 2;
        float4 t = *(const float4*)(Z + (long long)(zb * 64 + r) * CBD + c);
        Zs[r][c] = t.x; Zs[r][c + 1] = t.y; Zs[r][c + 2] = t.z; Zs[r][c + 3] = t.w;
    }
    __syncthreads();

    float bestv[4]; int bestc[4];
#pragma unroll
    for (int i = 0; i < 4; i++) { bestv[i] = -1e30f; bestc[i] = sp * (CBSZ / NSPLIT); }

    const int cbeg = sp * (CBSZ / NSPLIT);
    const int cend = cbeg + (CBSZ / NSPLIT);
    for (int c0 = cbeg; c0 < cend; c0 += 64) {
#pragma unroll
        for (int v = 0; v < 4; v++) {
            int idx = tid + v * 256;
            int r = idx >> 4, c = (idx & 15) << 2;
            float4 t = *(const float4*)(cb + (long long)(c0 + r) * CBD + c);
            Cs[r][c] = t.x; Cs[r][c + 1] = t.y; Cs[r][c + 2] = t.z; Cs[r][c + 3] = t.w;
        }
        __syncthreads();
        float acc[4][4] = {};
#pragma unroll 8
        for (int d = 0; d < 64; d++) {
            float zv[4], cv[4];
#pragma unroll
            for (int i = 0; i < 4; i++) zv[i] = Zs[ty * 4 + i][d];
#pragma unroll
            for (int j = 0; j < 4; j++) cv[j] = Cs[tx * 4 + j][d];
#pragma unroll
            for (int i = 0; i < 4; i++)
#pragma unroll
                for (int j = 0; j < 4; j++) acc[i][j] += zv[i] * cv[j];
        }
#pragma unroll
        for (int i = 0; i < 4; i++)
#pragma unroll
            for (int j = 0; j < 4; j++) {
                int c = c0 + tx * 4 + j;
                float scv = acc[i][j] - g_cn[c];
                if (scv > bestv[i] || (scv == bestv[i] && c < bestc[i])) {
                    bestv[i] = scv; bestc[i] = c;
                }
            }
        __syncthreads();
    }
#pragma unroll
    for (int i = 0; i < 4; i++) {
        float v = bestv[i]; int c = bestc[i];
#pragma unroll
        for (int off = 8; off; off >>= 1) {
            float ov = __shfl_xor_sync(0xffffffffu, v, off);
            int   oc = __shfl_xor_sync(0xffffffffu, c, off);
            if (ov > v || (ov == v && oc < c)) { v = ov; c = oc; }
        }
        if (tx == 0) {
            g_bv[sp][zb * 64 + ty * 4 + i] = v;
            g_bc[sp][zb * 64 + ty * 4 + i] = c;
        }
    }
}

__global__ void vq_combine_k()
{
    int t = blockIdx.x * 256 + threadIdx.x;
    float bv = g_bv[0][t]; int bc = g_bc[0][t];
#pragma unroll
    for (int s = 1; s < NSPLIT; s++) {
        float v = g_bv[s][t]; int c = g_bc[s][t];
        if (v > bv) { bv = v; bc = c; }
    }
    g_idx[t] = bc;
}

__global__ void vq_reduce_k(const float* __restrict__ cb,
                            const float* __restrict__ Z,
                            float* __restrict__ out)
{
    __shared__ float ssum[256];
    __shared__ float sloss[256];
    const int b = blockIdx.x;
    const int tid = threadIdx.x;
    const int d = tid & 63;
    const int sg = tid >> 6;
    float sum = 0.f, loss = 0.f;
    for (int s = sg; s < SEQ; s += 4) {
        int c = g_idx[b * SEQ + s];
        float qv = cb[(long long)c * CBD + d];
        float zv = Z[((long long)b * SEQ + s) * CBD + d];
        sum += qv;
        float dd = qv - zv;
        loss += dd * dd;
    }
    ssum[tid] = sum; sloss[tid] = loss;
    __syncthreads();
    if (tid < 64)
        out[b * CBD + tid] = ssum[tid] + ssum[tid + 64] + ssum[tid + 128] + ssum[tid + 192];
    for (int st = 128; st > 0; st >>= 1) {
        if (tid < st) sloss[tid] += sloss[tid + st];
        __syncthreads();
    }
    if (tid == 0) g_part[b] = sloss[0];
}

__global__ void vq_finish_k(float* __restrict__ out, int out_size)
{
    if (threadIdx.x == 0 && out_size > NBAT * CBD) {
        float s = 0.f;
        for (int i = 0; i < NBAT; i++) s += g_part[i];
        out[NBAT * CBD] = s / (float)(TOK * CBD);
    }
}

// ---------------------------------------------------------------------------
// Launch
// ---------------------------------------------------------------------------
extern "C" void kernel_launch(void* const* d_in, const int* in_sizes, int n_in,
                              void* d_out, int out_size)
{
    (void)in_sizes; (void)n_in;
    const float* x    = (const float*)d_in[0];
    const float* w_in = (const float*)d_in[1];
    const float* b_in = (const float*)d_in[2];
    const float* pos  = (const float*)d_in[3];
    const float* ln1g = (const float*)d_in[4];
    const float* ln1b = (const float*)d_in[5];
    const float* wq   = (const float*)d_in[6];
    const float* wk   = (const float*)d_in[7];
    const float* wv   = (const float*)d_in[8];
    const float* wo   = (const float*)d_in[9];
    const float* ln2g = (const float*)d_in[10];
    const float* ln2b = (const float*)d_in[11];
    const float* fw1  = (const float*)d_in[12];
    const float* fb1  = (const float*)d_in[13];
    const float* fw2  = (const float*)d_in[14];
    const float* fb2  = (const float*)d_in[15];
    const float* lnfg = (const float*)d_in[16];
    const float* lnfb = (const float*)d_in[17];
    const float* wout = (const float*)d_in[18];
    const float* bout = (const float*)d_in[19];
    const float* cbk  = (const float*)d_in[20];
    float* out = (float*)d_out;

    float *h, *ln, *qb, *kb, *vb, *att, *ff, *z;
    cudaGetSymbolAddress((void**)&h,   g_h);
    cudaGetSymbolAddress((void**)&ln,  g_lnb);
    cudaGetSymbolAddress((void**)&qb,  g_qb);
    cudaGetSymbolAddress((void**)&kb,  g_kb);
    cudaGetSymbolAddress((void**)&vb,  g_vb);
    cudaGetSymbolAddress((void**)&att, g_att);
    cudaGetSymbolAddress((void**)&ff,  g_ffb);
    cudaGetSymbolAddress((void**)&z,   g_z);

    cudaFuncSetAttribute(tgemm_k, cudaFuncAttributeMaxDynamicSharedMemorySize, TG_SMEM);
    cudaFuncSetAttribute(fattn_k, cudaFuncAttributeMaxDynamicSharedMemorySize,
                         16640 * (int)sizeof(float));

    const dim3 g512(4, 64), g2048(16, 64), g64(1, 64);

    tgemm_k<<<g512, 256, TG_SMEM>>>(x, w_in, h, b_in, pos, DIMN, DIMN, EPI_BIAS_POS);

    for (int l = 0; l < 4; l++) {
        layernorm_k<<<TOK, 256>>>(h, ln, ln1g + l * DIMN, ln1b + l * DIMN);
        tgemm_k<<<g512, 256, TG_SMEM>>>(ln, wq + (long long)l * DIMN * DIMN, qb, nullptr, nullptr, DIMN, DIMN, EPI_NONE);
        tgemm_k<<<g512, 256, TG_SMEM>>>(ln, wk + (long long)l * DIMN * DIMN, kb, nullptr, nullptr, DIMN, DIMN, EPI_NONE);
        tgemm_k<<<g512, 256, TG_SMEM>>>(ln, wv + (long long)l * DIMN * DIMN, vb, nullptr, nullptr, DIMN, DIMN, EPI_NONE);
        fattn_k<<<dim3(8, 128), 256, 16640 * sizeof(float)>>>(qb, kb, vb, att);
        tgemm_k<<<g512, 256, TG_SMEM>>>(att, wo + (long long)l * DIMN * DIMN, h, nullptr, h, DIMN, DIMN, EPI_RES);
        layernorm_k<<<TOK, 256>>>(h, ln, ln2g + l * DIMN, ln2b + l * DIMN);
        tgemm_k<<<g2048, 256, TG_SMEM>>>(ln, fw1 + (long long)l * DIMN * FFD, ff, fb1 + l * FFD, nullptr, FFD, DIMN, EPI_GELU_BIAS);
        tgemm_k<<<g512, 256, TG_SMEM>>>(ff, fw2 + (long long)l * FFD * DIMN, h, fb2 + l * DIMN, h, DIMN, FFD, EPI_RES_BIAS);
    }

    layernorm_k<<<TOK, 256>>>(h, ln, lnfg, lnfb);
    tgemm_k<<<g64, 256, TG_SMEM>>>(ln, wout, z, bout, nullptr, CBD, DIMN, EPI_BIAS);

    cb_norm_k<<<CBSZ / 256, 256>>>(cbk);
    vq_argmin_k<<<dim3(TOK / 64, NSPLIT), 256>>>(z, cbk);
    vq_combine_k<<<TOK / 256, 256>>>();
    vq_reduce_k<<<NBAT, 256>>>(cbk, z, out);
    vq_finish_k<<<1, 32>>>(out, out_size);
}

// round 8
// speedup vs baseline: 1.5636x; 1.1635x over previous
#include <cuda_runtime.h>
#include <cuda_fp16.h>
#include <cstdint>

#define TOK   8192
#define DIMN  512
#define SEQ   512
#define NBAT  16
#define FFD   2048
#define CBSZ  8192
#define CBD   64
#define NSPLIT 4

__device__ float g_h  [TOK * DIMN];
__device__ float g_lnb[TOK * DIMN];
__device__ float g_qb [TOK * DIMN];
__device__ float g_kb [TOK * DIMN];
__device__ float g_vb [TOK * DIMN];
__device__ float g_att[TOK * DIMN];
__device__ float g_ffb[TOK * FFD];
__device__ float g_z  [TOK * CBD];
__device__ float g_cn [CBSZ];
__device__ float g_bv [NSPLIT][TOK];
__device__ int   g_bc [NSPLIT][TOK];
__device__ int   g_idx[TOK];
__device__ float g_part[NBAT];

enum { EPI_NONE = 0, EPI_BIAS = 1, EPI_BIAS_POS = 2, EPI_RES = 3,
       EPI_RES_BIAS = 4, EPI_GELU_BIAS = 5 };

__device__ __forceinline__ float gelu_f(float x) {
    float x3 = x * x * x;
    float t  = tanhf(0.7978845608028654f * (x + 0.044715f * x3));
    return 0.5f * x * (1.0f + t);
}

// pack two fp32 into (big half2) and (small half2)
__device__ __forceinline__ void split2(float x, float y,
                                       uint32_t& big, uint32_t& sml) {
    half bx = __float2half_rn(x);
    half by = __float2half_rn(y);
    half sx = __float2half_rn(x - __half2float(bx));
    half sy = __float2half_rn(y - __half2float(by));
    half2 b = __halves2half2(bx, by);
    half2 s = __halves2half2(sx, sy);
    big = *(uint32_t*)&b;
    sml = *(uint32_t*)&s;
}

// m16n8k16 fp16 MMA, f32 accum: D += A*B
__device__ __forceinline__ void mma16816(float* d, const uint32_t* a,
                                         uint32_t b0, uint32_t b1) {
    asm volatile(
        "mma.sync.aligned.m16n8k16.row.col.f32.f16.f16.f32 "
        "{%0,%1,%2,%3}, {%4,%5,%6,%7}, {%8,%9}, {%0,%1,%2,%3};"
        : "+f"(d[0]), "+f"(d[1]), "+f"(d[2]), "+f"(d[3])
        : "r"(a[0]), "r"(a[1]), "r"(a[2]), "r"(a[3]), "r"(b0), "r"(b1));
}

// ---------------------------------------------------------------------------
// fp16x3 GEMM, double-buffered (unchanged from R7 WIN)
// ---------------------------------------------------------------------------
#define BUF_W 10240
#define TG_SMEM (2 * BUF_W * 4)

__global__ __launch_bounds__(256, 2)
void tgemm_k(const float* __restrict__ A, const float* __restrict__ B,
             float* __restrict__ C, const float* __restrict__ bias,
             const float* __restrict__ extra, int Nn, int K, int epi)
{
    extern __shared__ uint32_t smw[];

    const int tid  = threadIdx.x;
    const int lane = tid & 31;
    const int w    = tid >> 5;
    const int wm   = w & 3;
    const int wn   = w >> 2;
    const int row0 = blockIdx.y * 128;
    const int col0 = blockIdx.x * 128;
    const int m0w  = wm * 32;
    const int n0w  = wn * 64;
    const int g    = lane >> 2;
    const int tg   = lane & 3;

    const int lar  = tid >> 2;
    const int lakq = (tid & 3) << 2;
    const int lbn  = tid & 127;
    const int lbkh = tid >> 7;
    const bool inb = (col0 + lbn) < Nn;

    float acc[2][8][4];
#pragma unroll
    for (int i = 0; i < 2; i++)
#pragma unroll
        for (int j = 0; j < 8; j++)
#pragma unroll
            for (int q = 0; q < 4; q++) acc[i][j][q] = 0.f;

    float4 pa[4];
    float  pbv[16];

#define LOAD_CHUNK(k0)                                                        \
    {                                                                         \
        _Pragma("unroll")                                                     \
        for (int v = 0; v < 2; v++)                                           \
            _Pragma("unroll")                                                 \
            for (int kb = 0; kb < 2; kb++)                                    \
                pa[v * 2 + kb] = *(const float4*)(A +                         \
                    (long long)(row0 + lar + v * 64) * K + (k0) + kb * 16 + lakq); \
        _Pragma("unroll")                                                     \
        for (int kk = 0; kk < 16; kk++) {                                     \
            pbv[kk] = 0.f;                                                    \
            if (inb)                                                          \
                pbv[kk] = B[(long long)((k0) + lbkh * 16 + kk) * Nn + col0 + lbn]; \
        }                                                                     \
    }

#define STORE_CHUNK(base)                                                     \
    {                                                                         \
        uint32_t* Abw = (base);                                               \
        uint32_t* Asw = (base) + 2560;                                        \
        uint32_t* Bbw = (base) + 5120;                                        \
        uint32_t* Bsw = (base) + 7680;                                        \
        _Pragma("unroll")                                                     \
        for (int v = 0; v < 2; v++)                                           \
            _Pragma("unroll")                                                 \
            for (int kb = 0; kb < 2; kb++) {                                  \
                float4 t = pa[v * 2 + kb];                                    \
                uint32_t b0, s0, b1, s1;                                      \
                split2(t.x, t.y, b0, s0);                                     \
                split2(t.z, t.w, b1, s1);                                     \
                int wo = (lar + v * 64) * 20 + kb * 8 + (lakq >> 1);          \
                Abw[wo] = b0; Abw[wo + 1] = b1;                               \
                Asw[wo] = s0; Asw[wo + 1] = s1;                               \
            }                                                                 \
        uint32_t bw[8], sw[8];                                                \
        _Pragma("unroll")                                                     \
        for (int p = 0; p < 8; p++)                                           \
            split2(pbv[2 * p], pbv[2 * p + 1], bw[p], sw[p]);                 \
        int bo = lbn * 20 + lbkh * 8;                                         \
        *(uint4*)(Bbw + bo)     = make_uint4(bw[0], bw[1], bw[2], bw[3]);     \
        *(uint4*)(Bbw + bo + 4) = make_uint4(bw[4], bw[5], bw[6], bw[7]);     \
        *(uint4*)(Bsw + bo)     = make_uint4(sw[0], sw[1], sw[2], sw[3]);     \
        *(uint4*)(Bsw + bo + 4) = make_uint4(sw[4], sw[5], sw[6], sw[7]);     \
    }

    LOAD_CHUNK(0)
    STORE_CHUNK(smw)
    __syncthreads();

    const int nc = K >> 5;
    for (int c = 0; c < nc; c++) {
        const int p = c & 1;
        uint32_t* Abw = smw + p * BUF_W;
        uint32_t* Asw = Abw + 2560;
        uint32_t* Bbw = Abw + 5120;
        uint32_t* Bsw = Abw + 7680;

        if (c + 1 < nc) LOAD_CHUNK((c + 1) << 5)

#pragma unroll
        for (int ks = 0; ks < 2; ks++) {
            const int ko = ks << 3;
            uint32_t fab[2][4], fas[2][4];
#pragma unroll
            for (int i = 0; i < 2; i++) {
                int rb = m0w + i * 16 + g;
                fab[i][0] = Abw[rb * 20 + ko + tg];
                fab[i][1] = Abw[(rb + 8) * 20 + ko + tg];
                fab[i][2] = Abw[rb * 20 + ko + tg + 4];
                fab[i][3] = Abw[(rb + 8) * 20 + ko + tg + 4];
                fas[i][0] = Asw[rb * 20 + ko + tg];
                fas[i][1] = Asw[(rb + 8) * 20 + ko + tg];
                fas[i][2] = Asw[rb * 20 + ko + tg + 4];
                fas[i][3] = Asw[(rb + 8) * 20 + ko + tg + 4];
            }
#pragma unroll
            for (int j = 0; j < 8; j++) {
                int nb = n0w + j * 8 + g;
                uint32_t bb0 = Bbw[nb * 20 + ko + tg];
                uint32_t bb1 = Bbw[nb * 20 + ko + tg + 4];
                uint32_t bs0 = Bsw[nb * 20 + ko + tg];
                uint32_t bs1 = Bsw[nb * 20 + ko + tg + 4];
#pragma unroll
                for (int i = 0; i < 2; i++) {
                    mma16816(acc[i][j], fab[i], bb0, bb1);
                    mma16816(acc[i][j], fab[i], bs0, bs1);
                    mma16816(acc[i][j], fas[i], bb0, bb1);
                }
            }
        }

        if (c + 1 < nc) {
            STORE_CHUNK(smw + (p ^ 1) * BUF_W)
            __syncthreads();
        }
    }
#undef LOAD_CHUNK
#undef STORE_CHUNK

#pragma unroll
    for (int i = 0; i < 2; i++) {
        int r = row0 + m0w + i * 16 + g;
#pragma unroll
        for (int j = 0; j < 8; j++) {
            int cc = col0 + n0w + j * 8 + 2 * tg;
            if (cc >= Nn) continue;
            float2 v0 = make_float2(acc[i][j][0], acc[i][j][1]);
            float2 v1 = make_float2(acc[i][j][2], acc[i][j][3]);
            if (epi == EPI_BIAS || epi == EPI_RES_BIAS ||
                epi == EPI_GELU_BIAS || epi == EPI_BIAS_POS) {
                float2 b2 = *(const float2*)(bias + cc);
                v0.x += b2.x; v0.y += b2.y;
                v1.x += b2.x; v1.y += b2.y;
            }
            if (epi == EPI_BIAS_POS) {
                float2 p0 = *(const float2*)(extra + (long long)(r & (SEQ - 1)) * Nn + cc);
                float2 p1 = *(const float2*)(extra + (long long)((r + 8) & (SEQ - 1)) * Nn + cc);
                v0.x += p0.x; v0.y += p0.y;
                v1.x += p1.x; v1.y += p1.y;
            }
            if (epi == EPI_RES || epi == EPI_RES_BIAS) {
                float2 e0 = *(const float2*)(extra + (long long)r * Nn + cc);
                float2 e1 = *(const float2*)(extra + (long long)(r + 8) * Nn + cc);
                v0.x += e0.x; v0.y += e0.y;
                v1.x += e1.x; v1.y += e1.y;
            }
            if (epi == EPI_GELU_BIAS) {
                v0.x = gelu_f(v0.x); v0.y = gelu_f(v0.y);
                v1.x = gelu_f(v1.x); v1.y = gelu_f(v1.y);
            }
            *(float2*)(C + (long long)r * Nn + cc) = v0;
            *(float2*)(C + (long long)(r + 8) * Nn + cc) = v1;
        }
    }
}

// ---------------------------------------------------------------------------
// LayerNorm (row = 512)
// ---------------------------------------------------------------------------
__global__ void layernorm_k(const float* __restrict__ X, float* __restrict__ Y,
                            const float* __restrict__ gg, const float* __restrict__ bb)
{
    __shared__ float sm[16];
    const int row = blockIdx.x;
    const int t   = threadIdx.x;
    const float* x = X + (long long)row * DIMN;
    float v0 = x[t], v1 = x[t + 256];
    float s = v0 + v1;
    float q = v0 * v0 + v1 * v1;
#pragma unroll
    for (int off = 16; off; off >>= 1) {
        s += __shfl_xor_sync(0xffffffffu, s, off);
        q += __shfl_xor_sync(0xffffffffu, q, off);
    }
    if ((t & 31) == 0) { sm[t >> 5] = s; sm[8 + (t >> 5)] = q; }
    __syncthreads();
    float S = 0.f, Q = 0.f;
#pragma unroll
    for (int i = 0; i < 8; i++) { S += sm[i]; Q += sm[8 + i]; }
    float mu  = S * (1.0f / DIMN);
    float var = Q * (1.0f / DIMN) - mu * mu;
    float inv = 1.0f / sqrtf(var + 1e-5f);
    Y[(long long)row * DIMN + t]       = (v0 - mu) * inv * gg[t]       + bb[t];
    Y[(long long)row * DIMN + t + 256] = (v1 - mu) * inv * gg[t + 256] + bb[t + 256];
}

// ---------------------------------------------------------------------------
// Fused flash attention via fp16x3 MMA.
// Block = 128 threads (4 warps), grid (8 qtiles, 128 bh).
// Warp w owns q rows [qt*64 + w*16, +16). Per ktile of 64:
//   S = Q K^T (3-pass fp16 MMA) -> online softmax in regs -> O += P V (3-pass).
// smem (uint32 words, stride 36/row): Qb,Qs,Kb,Ks [row][dhpair]; Vb,Vs [dh][seqpair]
// ---------------------------------------------------------------------------
#define FA_QB 0
#define FA_QS 2304
#define FA_KB 4608
#define FA_KS 6912
#define FA_VB 9216
#define FA_VS 11520
#define FA_SMEM (13824 * 4)

__global__ __launch_bounds__(128)
void fattn_k(const float* __restrict__ Q, const float* __restrict__ K,
             const float* __restrict__ V, float* __restrict__ O)
{
    extern __shared__ uint32_t fsm[];
    const int tid  = threadIdx.x;
    const int lane = tid & 31;
    const int w    = tid >> 5;
    const int g    = lane >> 2;
    const int tg   = lane & 3;
    const int qt   = blockIdx.x, bh = blockIdx.y;
    const int b    = bh >> 3, h = bh & 7;

    const float* Qg = Q + ((long long)(b * SEQ + qt * 64)) * DIMN + h * 64;

    // ---- stage Q tile (64x64) split into smem ----
#pragma unroll
    for (int i = 0; i < 8; i++) {
        int f = tid + (i << 7);
        int r = f >> 4, cq = f & 15;
        float4 v = *(const float4*)(Qg + (long long)r * DIMN + cq * 4);
        uint32_t b0, s0, b1, s1;
        split2(v.x, v.y, b0, s0);
        split2(v.z, v.w, b1, s1);
        int o = r * 36 + cq * 2;
        fsm[FA_QB + o] = b0; fsm[FA_QB + o + 1] = b1;
        fsm[FA_QS + o] = s0; fsm[FA_QS + o + 1] = s1;
    }
    __syncthreads();

    // ---- Q fragments (persist across ktiles) ----
    uint32_t qfb[4][4], qfs[4][4];
    const int qr = w * 16 + g;
#pragma unroll
    for (int kg = 0; kg < 4; kg++) {
        int ba = qr * 36 + kg * 8 + tg;
        qfb[kg][0] = fsm[FA_QB + ba];
        qfb[kg][1] = fsm[FA_QB + ba + 288];       // +8 rows * 36
        qfb[kg][2] = fsm[FA_QB + ba + 4];
        qfb[kg][3] = fsm[FA_QB + ba + 292];
        qfs[kg][0] = fsm[FA_QS + ba];
        qfs[kg][1] = fsm[FA_QS + ba + 288];
        qfs[kg][2] = fsm[FA_QS + ba + 4];
        qfs[kg][3] = fsm[FA_QS + ba + 292];
    }

    float m0 = -1e30f, m1 = -1e30f, l0 = 0.f, l1 = 0.f;
    float oa[8][4];
#pragma unroll
    for (int j = 0; j < 8; j++)
#pragma unroll
        for (int q = 0; q < 4; q++) oa[j][q] = 0.f;

    const int r2  = tid & 31;      // V loader: seq pair index
    const int cgV = tid >> 5;      // V loader: dh group

    for (int kt = 0; kt < 8; kt++) {
        const float* Kg = K + ((long long)(b * SEQ + kt * 64)) * DIMN + h * 64;
        const float* Vg = V + ((long long)(b * SEQ + kt * 64)) * DIMN + h * 64;

        __syncthreads();   // previous iteration's MMAs done before overwrite
        // K tile [seq r][dh c] split
#pragma unroll
        for (int i = 0; i < 8; i++) {
            int f = tid + (i << 7);
            int r = f >> 4, cq = f & 15;
            float4 v = *(const float4*)(Kg + (long long)r * DIMN + cq * 4);
            uint32_t b0, s0, b1, s1;
            split2(v.x, v.y, b0, s0);
            split2(v.z, v.w, b1, s1);
            int o = r * 36 + cq * 2;
            fsm[FA_KB + o] = b0; fsm[FA_KB + o + 1] = b1;
            fsm[FA_KS + o] = s0; fsm[FA_KS + o + 1] = s1;
        }
        // V tile transposed [dh c][seq pair r2]
#pragma unroll
        for (int i = 0; i < 4; i++) {
            int c0 = cgV * 16 + i * 4;
            float4 va = *(const float4*)(Vg + (long long)(2 * r2) * DIMN + c0);
            float4 vb = *(const float4*)(Vg + (long long)(2 * r2 + 1) * DIMN + c0);
            float av[4] = {va.x, va.y, va.z, va.w};
            float bv[4] = {vb.x, vb.y, vb.z, vb.w};
#pragma unroll
            for (int k = 0; k < 4; k++) {
                uint32_t big, sml;
                split2(av[k], bv[k], big, sml);
                fsm[FA_VB + (c0 + k) * 36 + r2] = big;
                fsm[FA_VS + (c0 + k) * 36 + r2] = sml;
            }
        }
        __syncthreads();

        // ---- S = Q K^T (scaled later) ----
        float s[8][4];
#pragma unroll
        for (int j = 0; j < 8; j++)
#pragma unroll
            for (int q = 0; q < 4; q++) s[j][q] = 0.f;
#pragma unroll
        for (int j = 0; j < 8; j++) {
            int nb = j * 8 + g;
#pragma unroll
            for (int kg = 0; kg < 4; kg++) {
                int ko = kg * 8 + tg;
                uint32_t kb0 = fsm[FA_KB + nb * 36 + ko];
                uint32_t kb1 = fsm[FA_KB + nb * 36 + ko + 4];
                uint32_t ks0 = fsm[FA_KS + nb * 36 + ko];
                uint32_t ks1 = fsm[FA_KS + nb * 36 + ko + 4];
                mma16816(s[j], qfb[kg], kb0, kb1);
                mma16816(s[j], qfb[kg], ks0, ks1);
                mma16816(s[j], qfs[kg], kb0, kb1);
            }
        }

        // ---- online softmax (rows g and g+8 live on this lane group) ----
        float ml0 = -1e30f, ml1 = -1e30f;
#pragma unroll
        for (int j = 0; j < 8; j++) {
            s[j][0] *= 0.125f; s[j][1] *= 0.125f;
            s[j][2] *= 0.125f; s[j][3] *= 0.125f;
            ml0 = fmaxf(ml0, fmaxf(s[j][0], s[j][1]));
            ml1 = fmaxf(ml1, fmaxf(s[j][2], s[j][3]));
        }
        ml0 = fmaxf(ml0, __shfl_xor_sync(0xffffffffu, ml0, 1));
        ml0 = fmaxf(ml0, __shfl_xor_sync(0xffffffffu, ml0, 2));
        ml1 = fmaxf(ml1, __shfl_xor_sync(0xffffffffu, ml1, 1));
        ml1 = fmaxf(ml1, __shfl_xor_sync(0xffffffffu, ml1, 2));
        float mn0 = fmaxf(m0, ml0), mn1 = fmaxf(m1, ml1);
        float sc0 = __expf(m0 - mn0), sc1 = __expf(m1 - mn1);
        float rs0 = 0.f, rs1 = 0.f;
#pragma unroll
        for (int j = 0; j < 8; j++) {
            s[j][0] = __expf(s[j][0] - mn0);
            s[j][1] = __expf(s[j][1] - mn0);
            s[j][2] = __expf(s[j][2] - mn1);
            s[j][3] = __expf(s[j][3] - mn1);
            rs0 += s[j][0] + s[j][1];
            rs1 += s[j][2] + s[j][3];
        }
        rs0 += __shfl_xor_sync(0xffffffffu, rs0, 1);
        rs0 += __shfl_xor_sync(0xffffffffu, rs0, 2);
        rs1 += __shfl_xor_sync(0xffffffffu, rs1, 1);
        rs1 += __shfl_xor_sync(0xffffffffu, rs1, 2);
        l0 = l0 * sc0 + rs0;
        l1 = l1 * sc1 + rs1;
        m0 = mn0; m1 = mn1;
#pragma unroll
        for (int j = 0; j < 8; j++) {
            oa[j][0] *= sc0; oa[j][1] *= sc0;
            oa[j][2] *= sc1; oa[j][3] *= sc1;
        }

        // ---- P fragments directly from S fragments (no smem) ----
        uint32_t pab[4][4], pas[4][4];
#pragma unroll
        for (int kg = 0; kg < 4; kg++) {
            int j0 = 2 * kg, j1 = 2 * kg + 1;
            split2(s[j0][0], s[j0][1], pab[kg][0], pas[kg][0]);
            split2(s[j0][2], s[j0][3], pab[kg][1], pas[kg][1]);
            split2(s[j1][0], s[j1][1], pab[kg][2], pas[kg][2]);
            split2(s[j1][2], s[j1][3], pab[kg][3], pas[kg][3]);
        }

        // ---- O += P V ----
#pragma unroll
        for (int jo = 0; jo < 8; jo++) {
            int nb = jo * 8 + g;
#pragma unroll
            for (int kg = 0; kg < 4; kg++) {
                int ko = kg * 8 + tg;
                uint32_t vb0 = fsm[FA_VB + nb * 36 + ko];
                uint32_t vb1 = fsm[FA_VB + nb * 36 + ko + 4];
                uint32_t vs0 = fsm[FA_VS + nb * 36 + ko];
                uint32_t vs1 = fsm[FA_VS + nb * 36 + ko + 4];
                mma16816(oa[jo], pab[kg], vb0, vb1);
                mma16816(oa[jo], pab[kg], vs0, vs1);
                mma16816(oa[jo], pas[kg], vb0, vb1);
            }
        }
    }

    // ---- write O ----
    float inv0 = 1.0f / l0, inv1 = 1.0f / l1;
    int row0 = b * SEQ + qt * 64 + w * 16 + g;
#pragma unroll
    for (int jo = 0; jo < 8; jo++) {
        int col = h * 64 + jo * 8 + 2 * tg;
        *(float2*)(O + (long long)row0 * DIMN + col) =
            make_float2(oa[jo][0] * inv0, oa[jo][1] * inv0);
        *(float2*)(O + (long long)(row0 + 8) * DIMN + col) =
            make_float2(oa[jo][2] * inv1, oa[jo][3] * inv1);
    }
}

// ---------------------------------------------------------------------------
// VQ
// ---------------------------------------------------------------------------
__global__ void cb_norm_k(const float* __restrict__ cb)
{
    int c = blockIdx.x * 256 + threadIdx.x;
    float s = 0.f;
    const float* p = cb + (long long)c * CBD;
#pragma unroll 8
    for (int d = 0; d < CBD; d++) { float v = p[d]; s += v * v; }
    g_cn[c] = 0.5f * s;
}

__global__ __launch_bounds__(256)
void vq_argmin_k(const float* __restrict__ Z, const float* __restrict__ cb)
{
    const int zb = blockIdx.x;
    const int sp = blockIdx.y;
    __shared__ float Zs[64][65];
    __shared__ float Cs[64][65];
    const int tid = threadIdx.x;
    const int ty = tid >> 4, tx = tid & 15;
#pragma unroll
    for (int v = 0; v < 4; v++) {
        int idx = tid + v * 256;
        int r = idx >> 4, c = (idx & 15) << 2;
        float4 t = *(const float4*)(Z + (long long)(zb * 64 + r) * CBD + c);
        Zs[r][c] = t.x; Zs[r][c + 1] = t.y; Zs[r][c + 2] = t.z; Zs[r][c + 3] = t.w;
    }
    __syncthreads();

    float bestv[4]; int bestc[4];
#pragma unroll
    for (int i = 0; i < 4; i++) { bestv[i] = -1e30f; bestc[i] = sp * (CBSZ / NSPLIT); }

    const int cbeg = sp * (CBSZ / NSPLIT);
    const int cend = cbeg + (CBSZ / NSPLIT);
    for (int c0 = cbeg; c0 < cend; c0 += 64) {
#pragma unroll
        for (int v = 0; v < 4; v++) {
            int idx = tid + v * 256;
            int r = idx >> 4, c = (idx & 15) << 2;
            float4 t = *(const float4*)(cb + (long long)(c0 + r) * CBD + c);
            Cs[r][c] = t.x; Cs[r][c + 1] = t.y; Cs[r][c + 2] = t.z; Cs[r][c + 3] = t.w;
        }
        __syncthreads();
        float acc[4][4] = {};
#pragma unroll 8
        for (int d = 0; d < 64; d++) {
            float zv[4], cv[4];
#pragma unroll
            for (int i = 0; i < 4; i++) zv[i] = Zs[ty * 4 + i][d];
#pragma unroll
            for (int j = 0; j < 4; j++) cv[j] = Cs[tx * 4 + j][d];
#pragma unroll
            for (int i = 0; i < 4; i++)
#pragma unroll
                for (int j = 0; j < 4; j++) acc[i][j] += zv[i] * cv[j];
        }
#pragma unroll
        for (int i = 0; i < 4; i++)
#pragma unroll
            for (int j = 0; j < 4; j++) {
                int c = c0 + tx * 4 + j;
                float scv = acc[i][j] - g_cn[c];
                if (scv > bestv[i] || (scv == bestv[i] && c < bestc[i])) {
                    bestv[i] = scv; bestc[i] = c;
                }
            }
        __syncthreads();
    }
#pragma unroll
    for (int i = 0; i < 4; i++) {
        float v = bestv[i]; int c = bestc[i];
#pragma unroll
        for (int off = 8; off; off >>= 1) {
            float ov = __shfl_xor_sync(0xffffffffu, v, off);
            int   oc = __shfl_xor_sync(0xffffffffu, c, off);
            if (ov > v || (ov == v && oc < c)) { v = ov; c = oc; }
        }
        if (tx == 0) {
            g_bv[sp][zb * 64 + ty * 4 + i] = v;
            g_bc[sp][zb * 64 + ty * 4 + i] = c;
        }
    }
}

__global__ void vq_combine_k()
{
    int t = blockIdx.x * 256 + threadIdx.x;
    float bv = g_bv[0][t]; int bc = g_bc[0][t];
#pragma unroll
    for (int s = 1; s < NSPLIT; s++) {
        float v = g_bv[s][t]; int c = g_bc[s][t];
        if (v > bv) { bv = v; bc = c; }
    }
    g_idx[t] = bc;
}

__global__ void vq_reduce_k(const float* __restrict__ cb,
                            const float* __restrict__ Z,
                            float* __restrict__ out)
{
    __shared__ float ssum[256];
    __shared__ float sloss[256];
    const int b = blockIdx.x;
    const int tid = threadIdx.x;
    const int d = tid & 63;
    const int sg = tid >> 6;
    float sum = 0.f, loss = 0.f;
    for (int s = sg; s < SEQ; s += 4) {
        int c = g_idx[b * SEQ + s];
        float qv = cb[(long long)c * CBD + d];
        float zv = Z[((long long)b * SEQ + s) * CBD + d];
        sum += qv;
        float dd = qv - zv;
        loss += dd * dd;
    }
    ssum[tid] = sum; sloss[tid] = loss;
    __syncthreads();
    if (tid < 64)
        out[b * CBD + tid] = ssum[tid] + ssum[tid + 64] + ssum[tid + 128] + ssum[tid + 192];
    for (int st = 128; st > 0; st >>= 1) {
        if (tid < st) sloss[tid] += sloss[tid + st];
        __syncthreads();
    }
    if (tid == 0) g_part[b] = sloss[0];
}

__global__ void vq_finish_k(float* __restrict__ out, int out_size)
{
    if (threadIdx.x == 0 && out_size > NBAT * CBD) {
        float s = 0.f;
        for (int i = 0; i < NBAT; i++) s += g_part[i];
        out[NBAT * CBD] = s / (float)(TOK * CBD);
    }
}

// ---------------------------------------------------------------------------
// Launch
// ---------------------------------------------------------------------------
extern "C" void kernel_launch(void* const* d_in, const int* in_sizes, int n_in,
                              void* d_out, int out_size)
{
    (void)in_sizes; (void)n_in;
    const float* x    = (const float*)d_in[0];
    const float* w_in = (const float*)d_in[1];
    const float* b_in = (const float*)d_in[2];
    const float* pos  = (const float*)d_in[3];
    const float* ln1g = (const float*)d_in[4];
    const float* ln1b = (const float*)d_in[5];
    const float* wq   = (const float*)d_in[6];
    const float* wk   = (const float*)d_in[7];
    const float* wv   = (const float*)d_in[8];
    const float* wo   = (const float*)d_in[9];
    const float* ln2g = (const float*)d_in[10];
    const float* ln2b = (const float*)d_in[11];
    const float* fw1  = (const float*)d_in[12];
    const float* fb1  = (const float*)d_in[13];
    const float* fw2  = (const float*)d_in[14];
    const float* fb2  = (const float*)d_in[15];
    const float* lnfg = (const float*)d_in[16];
    const float* lnfb = (const float*)d_in[17];
    const float* wout = (const float*)d_in[18];
    const float* bout = (const float*)d_in[19];
    const float* cbk  = (const float*)d_in[20];
    float* out = (float*)d_out;

    float *h, *ln, *qb, *kb, *vb, *att, *ff, *z;
    cudaGetSymbolAddress((void**)&h,   g_h);
    cudaGetSymbolAddress((void**)&ln,  g_lnb);
    cudaGetSymbolAddress((void**)&qb,  g_qb);
    cudaGetSymbolAddress((void**)&kb,  g_kb);
    cudaGetSymbolAddress((void**)&vb,  g_vb);
    cudaGetSymbolAddress((void**)&att, g_att);
    cudaGetSymbolAddress((void**)&ff,  g_ffb);
    cudaGetSymbolAddress((void**)&z,   g_z);

    cudaFuncSetAttribute(tgemm_k, cudaFuncAttributeMaxDynamicSharedMemorySize, TG_SMEM);
    cudaFuncSetAttribute(fattn_k, cudaFuncAttributeMaxDynamicSharedMemorySize, FA_SMEM);

    const dim3 g512(4, 64), g2048(16, 64), g64(1, 64);

    tgemm_k<<<g512, 256, TG_SMEM>>>(x, w_in, h, b_in, pos, DIMN, DIMN, EPI_BIAS_POS);

    for (int l = 0; l < 4; l++) {
        layernorm_k<<<TOK, 256>>>(h, ln, ln1g + l * DIMN, ln1b + l * DIMN);
        tgemm_k<<<g512, 256, TG_SMEM>>>(ln, wq + (long long)l * DIMN * DIMN, qb, nullptr, nullptr, DIMN, DIMN, EPI_NONE);
        tgemm_k<<<g512, 256, TG_SMEM>>>(ln, wk + (long long)l * DIMN * DIMN, kb, nullptr, nullptr, DIMN, DIMN, EPI_NONE);
        tgemm_k<<<g512, 256, TG_SMEM>>>(ln, wv + (long long)l * DIMN * DIMN, vb, nullptr, nullptr, DIMN, DIMN, EPI_NONE);
        fattn_k<<<dim3(8, 128), 128, FA_SMEM>>>(qb, kb, vb, att);
        tgemm_k<<<g512, 256, TG_SMEM>>>(att, wo + (long long)l * DIMN * DIMN, h, nullptr, h, DIMN, DIMN, EPI_RES);
        layernorm_k<<<TOK, 256>>>(h, ln, ln2g + l * DIMN, ln2b + l * DIMN);
        tgemm_k<<<g2048, 256, TG_SMEM>>>(ln, fw1 + (long long)l * DIMN * FFD, ff, fb1 + l * FFD, nullptr, FFD, DIMN, EPI_GELU_BIAS);
        tgemm_k<<<g512, 256, TG_SMEM>>>(ff, fw2 + (long long)l * FFD * DIMN, h, fb2 + l * DIMN, h, DIMN, FFD, EPI_RES_BIAS);
    }

    layernorm_k<<<TOK, 256>>>(h, ln, lnfg, lnfb);
    tgemm_k<<<g64, 256, TG_SMEM>>>(ln, wout, z, bout, nullptr, CBD, DIMN, EPI_BIAS);

    cb_norm_k<<<CBSZ / 256, 256>>>(cbk);
    vq_argmin_k<<<dim3(TOK / 64, NSPLIT), 256>>>(z, cbk);
    vq_combine_k<<<TOK / 256, 256>>>();
    vq_reduce_k<<<NBAT, 256>>>(cbk, z, out);
    vq_finish_k<<<1, 32>>>(out, out_size);
}